// round 12
// baseline (speedup 1.0000x reference)
#include <cuda_runtime.h>

#define NTYPES 4
#define NDESC  8
#define KMAX   8
#define LMAX   4
#define MNBR   20
#define RCUT   5.0f
#define PI_F   3.14159265358979f

#define WPB     8
#define THREADS (WPB * 32)
#define REC_F4    7                  // 6 float4 used + 1 pad (STS conflict-free)
#define REC_F     (REC_F4 * 4)

typedef unsigned long long u64;

__device__ __forceinline__ u64 pk2(float lo, float hi) {
    u64 r; asm("mov.b64 %0,{%1,%2};" : "=l"(r) : "f"(lo), "f"(hi)); return r;
}
__device__ __forceinline__ void upk2(u64 v, float& lo, float& hi) {
    asm("mov.b64 {%0,%1},%2;" : "=f"(lo), "=f"(hi) : "l"(v));
}
__device__ __forceinline__ u64 fma2(u64 a, u64 b, u64 c) {
    u64 d; asm("fma.rn.f32x2 %0,%1,%2,%3;" : "=l"(d) : "l"(a), "l"(b), "l"(c)); return d;
}
__device__ __forceinline__ u64 mul2(u64 a, u64 b) {
    u64 d; asm("mul.rn.f32x2 %0,%1,%2;" : "=l"(d) : "l"(a), "l"(b)); return d;
}

__global__ __launch_bounds__(THREADS)
void angular_desc_kernel(const int*   __restrict__ types,
                         const float* __restrict__ positions,
                         const int*   __restrict__ nbrs,
                         const float* __restrict__ c_table,
                         float*       __restrict__ out,
                         int N)
{
    __shared__ float4 sh_e[WPB][MNBR][REC_F4];

    const int tid  = threadIdx.x;
    const int warp = tid >> 5;
    const int lane = tid & 31;
    const int atom = blockIdx.x * WPB + warp;
    if (atom >= N) return;
    const bool edge_lane = (lane < MNBR);

    // ---------------- issue the FULL dependent gmem chain first ----------------
    const int   ti  = types[atom];
    const float pix = positions[atom * 3 + 0];
    const float piy = positions[atom * 3 + 1];
    const float piz = positions[atom * 3 + 2];
    int j = 0;
    if (edge_lane) j = nbrs[atom * MNBR + lane];

    float ejx = 0.f, ejy = 0.f, ejz = 0.f; int tj = 0;
    if (edge_lane) {
        ejx = positions[j * 3 + 0];
        ejy = positions[j * 3 + 1];
        ejz = positions[j * 3 + 2];
        tj  = types[j];
    }

    // ---------------- Phase 1: per-edge records (lanes 0..19): g[8] and Z[16] ----------------
    if (edge_lane) {
        // c_table row for (ti,tj): 64 floats = 16 x ulonglong2. 4KB table is
        // L1-resident after first touch; issue all 16 independent 16B loads up front.
        const ulonglong2* crow =
            (const ulonglong2*)(c_table + (ti * NTYPES + tj) * (NDESC * KMAX));
        ulonglong2 cc[16];
        #pragma unroll
        for (int q = 0; q < 16; q++) cc[q] = __ldg(&crow[q]);  // cc[2d], cc[2d+1] per desc

        float dx = ejx - pix;
        float dy = ejy - piy;
        float dz = ejz - piz;

        float n2  = dx * dx + dy * dy + dz * dz;
        float inv = rsqrtf(n2);
        float r   = n2 * inv;
        float x = dx * inv, y = dy * inv, z = dz * inv;

        // Chebyshev radial basis, short-depth via T_{m+n} = 2 T_m T_n - T_|m-n|
        float fc  = (r < RCUT) ? (0.5f * __cosf(PI_F * r * (1.0f / RCUT)) + 0.5f) : 0.0f;
        float hfc = 0.5f * fc;
        float xr  = r * (1.0f / RCUT) - 1.0f;
        float t1  = 2.0f * xr * xr - 1.0f;            // x (= T1 of the shifted arg)
        float t2  = 2.0f * t1 * t1 - 1.0f;            // depth 1
        float t3  = 2.0f * t1 * t2 - t1;              // depth 2
        float t4  = 2.0f * t2 * t2 - 1.0f;            // depth 2
        float t5  = 2.0f * t2 * t3 - t1;              // depth 3
        float t6  = 2.0f * t3 * t3 - 1.0f;            // depth 3
        float t7  = 2.0f * t3 * t4 - t1;              // depth 3
        float fv0 = 2.0f * hfc;                       // (T0+1)*hfc
        float fv1 = (t1 + 1.0f) * hfc;
        float fv2 = (t2 + 1.0f) * hfc;
        float fv3 = (t3 + 1.0f) * hfc;
        float fv4 = (t4 + 1.0f) * hfc;
        float fv5 = (t5 + 1.0f) * hfc;
        float fv6 = (t6 + 1.0f) * hfc;
        float fv7 = (t7 + 1.0f) * hfc;

        // packed contraction: g[d] = c_row[d] . fv  via f32x2
        const u64 f01 = pk2(fv0, fv1);
        const u64 f23 = pk2(fv2, fv3);
        const u64 f45 = pk2(fv4, fv5);
        const u64 f67 = pk2(fv6, fv7);
        float g[NDESC];
        #pragma unroll
        for (int d = 0; d < NDESC; d++) {
            u64 acc = mul2(cc[2 * d].x, f01);
            acc = fma2(cc[2 * d].y,     f23, acc);
            acc = fma2(cc[2 * d + 1].x, f45, acc);
            acc = fma2(cc[2 * d + 1].y, f67, acc);
            float lo, hi; upk2(acc, lo, hi);
            g[d] = lo + hi;
        }

        // Real spherical harmonics Z_lm scaled so P_l(u.v) = sum_m Z_lm(u) Z_lm(v)
        float x2 = x * x, y2 = y * y, z2 = z * z;
        const float SQ3  = 1.73205080757f;
        const float SQ3H = 0.86602540378f;
        const float C31  = 0.61237243570f;   // sqrt(6)/4
        const float C32a = 3.87298334621f;   // sqrt(15)
        const float C32b = 1.93649167310f;   // sqrt(15)/2
        const float C33  = 0.79056941504f;   // sqrt(10)/4
        float a5z = 5.0f * z2 - 1.0f;

        sh_e[warp][lane][0] = make_float4(g[0], g[1], g[2], g[3]);
        sh_e[warp][lane][1] = make_float4(g[4], g[5], g[6], g[7]);
        sh_e[warp][lane][2] = make_float4(1.0f, x, y, z);
        sh_e[warp][lane][3] = make_float4(SQ3 * x * y, SQ3 * y * z, SQ3 * x * z, SQ3H * (x2 - y2));
        sh_e[warp][lane][4] = make_float4(0.5f * (3.0f * z2 - 1.0f),
                                          C33 * y * (3.0f * x2 - y2),
                                          C32a * x * y * z,
                                          C31 * y * a5z);
        sh_e[warp][lane][5] = make_float4(0.5f * z * (5.0f * z2 - 3.0f),
                                          C31 * x * a5z,
                                          C32b * z * (x2 - y2),
                                          C33 * x * (x2 - 3.0f * y2));
    }
    __syncwarp();

    // ---------------- Phase 2: S[d][m] = sum_j g_d(j) Z_m(j) (packed f32x2) ----------------
    const int d  = lane & 7;
    const int mg = lane >> 3;
    const float* rec = (const float*)&sh_e[warp][0][0];

    u64 S01 = 0ull, S23 = 0ull;
    float gg = 0.0f;
    #pragma unroll
    for (int jb = 0; jb < MNBR; jb += 4) {
        float      gv[4];
        ulonglong2 zz[4];
        #pragma unroll
        for (int u = 0; u < 4; u++) {
            const float* base = rec + (jb + u) * REC_F;
            gv[u] = base[d];                                    // broadcast within d-group
            zz[u] = *(const ulonglong2*)(base + 8 + 4 * mg);    // packed (z0z1)(z2z3)
        }
        #pragma unroll
        for (int u = 0; u < 4; u++) {
            u64 gs = pk2(gv[u], gv[u]);
            S01 = fma2(gs, zz[u].x, S01);
            S23 = fma2(gs, zz[u].y, S23);
            gg  = fmaf(gv[u], gv[u], gg);
        }
    }
    float S0, S1, S2, S3;
    upk2(S01, S0, S1);
    upk2(S23, S2, S3);

    // Sums of squares split by l within each m-group:
    // mg0: m0(l0) | m1..3(l1);  mg1: m4..7(l2);  mg2: m8(l2) | m9..11(l3);  mg3: m12..15(l3)
    float PA, PB;
    if (mg == 0 || mg == 2) {
        PA = S0 * S0;
        PB = S1 * S1 + S2 * S2 + S3 * S3;
    } else {
        PA = S0 * S0 + S1 * S1 + S2 * S2 + S3 * S3;
        PB = 0.0f;
    }

    // ---------------- Phase 3: recombine to output lane ----------------
    const int lo = lane & 3;
    const int od = lane >> 2;

    int srcA = (lo == 0) ? od : (lo == 2) ? (8 + od) : (lo == 3) ? (24 + od) : od;
    float vA = __shfl_sync(0xffffffffu, PA, srcA);
    int srcB = (lo == 1) ? od : (16 + od);
    float vB = __shfl_sync(0xffffffffu, PB, srcB);
    float vC = __shfl_sync(0xffffffffu, PA, 16 + od);
    float ggv = __shfl_sync(0xffffffffu, gg, od);

    float sumsq;
    if      (lo == 0) sumsq = vA;
    else if (lo == 1) sumsq = vB;
    else if (lo == 2) sumsq = vA + vC;
    else              sumsq = vA + vB;

    out[atom * (NDESC * LMAX) + lane] = 0.5f * (sumsq - ggv);
}

extern "C" void kernel_launch(void* const* d_in, const int* in_sizes, int n_in,
                              void* d_out, int out_size)
{
    const int*   types     = (const int*)d_in[0];
    const float* positions = (const float*)d_in[1];
    const int*   nbrs      = (const int*)d_in[2];
    const float* c_table   = (const float*)d_in[3];
    float*       out       = (float*)d_out;

    const int N = in_sizes[0];
    const int blocks = (N + WPB - 1) / WPB;
    angular_desc_kernel<<<blocks, THREADS>>>(types, positions, nbrs, c_table, out, N);
}

// round 13
// speedup vs baseline: 1.8136x; 1.8136x over previous
#include <cuda_runtime.h>

#define NTYPES 4
#define NDESC  8
#define KMAX   8
#define LMAX   4
#define MNBR   20
#define RCUT   5.0f
#define PI_F   3.14159265358979f

#define WPB     8
#define THREADS (WPB * 32)
#define CT_ROWS   (NTYPES * NTYPES)
#define CT_STRIDE 68                 // 68 % 32 == 4; 272B rows keep 16B alignment
#define G_STRIDE  28                 // words per d-row: d*28 mod 32 all-distinct, 16B-aligned

typedef unsigned long long u64;

__device__ __forceinline__ u64 pk2(float lo, float hi) {
    u64 r; asm("mov.b64 %0,{%1,%2};" : "=l"(r) : "f"(lo), "f"(hi)); return r;
}
__device__ __forceinline__ void upk2(u64 v, float& lo, float& hi) {
    asm("mov.b64 {%0,%1},%2;" : "=f"(lo), "=f"(hi) : "l"(v));
}
__device__ __forceinline__ u64 fma2(u64 a, u64 b, u64 c) {
    u64 d; asm("fma.rn.f32x2 %0,%1,%2,%3;" : "=l"(d) : "l"(a), "l"(b), "l"(c)); return d;
}
__device__ __forceinline__ u64 mul2(u64 a, u64 b) {
    u64 d; asm("mul.rn.f32x2 %0,%1,%2;" : "=l"(d) : "l"(a), "l"(b)); return d;
}

__global__ __launch_bounds__(THREADS)
void angular_desc_kernel(const int*   __restrict__ types,
                         const float* __restrict__ positions,
                         const int*   __restrict__ nbrs,
                         const float* __restrict__ c_table,
                         float*       __restrict__ out,
                         int N)
{
    __shared__ float  sh_ct[CT_ROWS * CT_STRIDE];
    __shared__ float  sh_g[WPB][NDESC][G_STRIDE];   // transposed g: [d][j]
    __shared__ float4 sh_z[WPB][MNBR][5];           // 4 float4 Z + 1 pad

    const int tid  = threadIdx.x;
    const int warp = tid >> 5;
    const int lane = tid & 31;
    const int atom = blockIdx.x * WPB + warp;
    const bool valid     = (atom < N);
    const bool edge_lane = valid && (lane < MNBR);

    // ---------------- issue the FULL dependent gmem chain first ----------------
    int j = 0, ti = 0;
    float pix = 0.f, piy = 0.f, piz = 0.f;
    if (valid) {
        ti  = types[atom];
        pix = positions[atom * 3 + 0];
        piy = positions[atom * 3 + 1];
        piz = positions[atom * 3 + 2];
    }
    if (edge_lane) j = nbrs[atom * MNBR + lane];

    float ejx = 0.f, ejy = 0.f, ejz = 0.f; int tj = 0;
    if (edge_lane) {
        ejx = positions[j * 3 + 0];
        ejy = positions[j * 3 + 1];
        ejz = positions[j * 3 + 2];
        tj  = types[j];
    }

    // ---------------- c_table staging: 1 LDG.128 + 1 STS.128 per thread ----------------
    {
        const float4 cv = ((const float4*)c_table)[tid];
        const int row = tid >> 4, col4 = tid & 15;
        *(float4*)&sh_ct[row * CT_STRIDE + col4 * 4] = cv;
    }
    __syncthreads();   // barrier wait absorbs tail of gmem chain

    if (!valid) return;

    // ---------------- Phase 1: per-edge records (lanes 0..19) ----------------
    if (edge_lane) {
        float dx = ejx - pix;
        float dy = ejy - piy;
        float dz = ejz - piz;

        float n2  = dx * dx + dy * dy + dz * dz;
        float inv = rsqrtf(n2);
        float r   = n2 * inv;
        float x = dx * inv, y = dy * inv, z = dz * inv;

        // Chebyshev radial basis, short depth via T_{m+n} = 2 T_m T_n - T_|m-n|
        float fc  = (r < RCUT) ? (0.5f * __cosf(PI_F * r * (1.0f / RCUT)) + 0.5f) : 0.0f;
        float hfc = 0.5f * fc;
        float xr  = r * (1.0f / RCUT) - 1.0f;
        float t1  = 2.0f * xr * xr - 1.0f;
        float t2  = 2.0f * t1 * t1 - 1.0f;
        float t3  = 2.0f * t1 * t2 - t1;
        float t4  = 2.0f * t2 * t2 - 1.0f;
        float t5  = 2.0f * t2 * t3 - t1;
        float t6  = 2.0f * t3 * t3 - 1.0f;
        float t7  = 2.0f * t3 * t4 - t1;
        float fv0 = 2.0f * hfc;
        float fv1 = (t1 + 1.0f) * hfc;
        float fv2 = (t2 + 1.0f) * hfc;
        float fv3 = (t3 + 1.0f) * hfc;
        float fv4 = (t4 + 1.0f) * hfc;
        float fv5 = (t5 + 1.0f) * hfc;
        float fv6 = (t6 + 1.0f) * hfc;
        float fv7 = (t7 + 1.0f) * hfc;

        // packed contraction: g[d] = c_row[d] . fv  via f32x2 (sh_ct: LDS broadcast-friendly)
        const u64 f01 = pk2(fv0, fv1);
        const u64 f23 = pk2(fv2, fv3);
        const u64 f45 = pk2(fv4, fv5);
        const u64 f67 = pk2(fv6, fv7);
        const float* crow = &sh_ct[(ti * NTYPES + tj) * CT_STRIDE];
        #pragma unroll
        for (int d = 0; d < NDESC; d++) {
            const ulonglong2 cA = *(const ulonglong2*)(crow + d * 8);
            const ulonglong2 cB = *(const ulonglong2*)(crow + d * 8 + 4);
            u64 acc = mul2(cA.x, f01);
            acc = fma2(cA.y, f23, acc);
            acc = fma2(cB.x, f45, acc);
            acc = fma2(cB.y, f67, acc);
            float lo, hi; upk2(acc, lo, hi);
            sh_g[warp][d][lane] = lo + hi;   // transposed store; banks = lane -> conflict-free
        }

        // Real spherical harmonics Z_lm scaled so P_l(u.v) = sum_m Z_lm(u) Z_lm(v)
        float x2 = x * x, y2 = y * y, z2 = z * z;
        const float SQ3  = 1.73205080757f;
        const float SQ3H = 0.86602540378f;
        const float C31  = 0.61237243570f;   // sqrt(6)/4
        const float C32a = 3.87298334621f;   // sqrt(15)
        const float C32b = 1.93649167310f;   // sqrt(15)/2
        const float C33  = 0.79056941504f;   // sqrt(10)/4
        float a5z = 5.0f * z2 - 1.0f;

        sh_z[warp][lane][0] = make_float4(1.0f, x, y, z);
        sh_z[warp][lane][1] = make_float4(SQ3 * x * y, SQ3 * y * z, SQ3 * x * z, SQ3H * (x2 - y2));
        sh_z[warp][lane][2] = make_float4(0.5f * (3.0f * z2 - 1.0f),
                                          C33 * y * (3.0f * x2 - y2),
                                          C32a * x * y * z,
                                          C31 * y * a5z);
        sh_z[warp][lane][3] = make_float4(0.5f * z * (5.0f * z2 - 3.0f),
                                          C31 * x * a5z,
                                          C32b * z * (x2 - y2),
                                          C33 * x * (x2 - 3.0f * y2));
    }
    __syncwarp();

    // ---------------- Phase 2: S[d][m] = sum_j g_d(j) Z_m(j) ----------------
    const int d  = lane & 7;
    const int mg = lane >> 3;

    u64 S01 = 0ull, S23 = 0ull;
    float gg = 0.0f;
    #pragma unroll
    for (int jb = 0; jb < MNBR; jb += 4) {
        // one LDS.128 fetches g_d for 4 records (8 distinct addrs, broadcast x4)
        const float4 gq = *(const float4*)&sh_g[warp][d][jb];
        ulonglong2 zz[4];
        #pragma unroll
        for (int u = 0; u < 4; u++)
            zz[u] = *(const ulonglong2*)&sh_z[warp][jb + u][mg];

        const float gv0 = gq.x, gv1 = gq.y, gv2 = gq.z, gv3 = gq.w;
        S01 = fma2(pk2(gv0, gv0), zz[0].x, S01);
        S23 = fma2(pk2(gv0, gv0), zz[0].y, S23);
        S01 = fma2(pk2(gv1, gv1), zz[1].x, S01);
        S23 = fma2(pk2(gv1, gv1), zz[1].y, S23);
        S01 = fma2(pk2(gv2, gv2), zz[2].x, S01);
        S23 = fma2(pk2(gv2, gv2), zz[2].y, S23);
        S01 = fma2(pk2(gv3, gv3), zz[3].x, S01);
        S23 = fma2(pk2(gv3, gv3), zz[3].y, S23);
        gg  = fmaf(gv0, gv0, gg);
        gg  = fmaf(gv1, gv1, gg);
        gg  = fmaf(gv2, gv2, gg);
        gg  = fmaf(gv3, gv3, gg);
    }
    float S0, S1, S2, S3;
    upk2(S01, S0, S1);
    upk2(S23, S2, S3);

    // Sums of squares split by l within each m-group:
    // mg0: m0(l0) | m1..3(l1);  mg1: m4..7(l2);  mg2: m8(l2) | m9..11(l3);  mg3: m12..15(l3)
    float PA, PB;
    if (mg == 0 || mg == 2) {
        PA = S0 * S0;
        PB = S1 * S1 + S2 * S2 + S3 * S3;
    } else {
        PA = S0 * S0 + S1 * S1 + S2 * S2 + S3 * S3;
        PB = 0.0f;
    }

    // ---------------- Phase 3: recombine to output lane ----------------
    const int lo = lane & 3;
    const int od = lane >> 2;

    int srcA = (lo == 0) ? od : (lo == 2) ? (8 + od) : (lo == 3) ? (24 + od) : od;
    float vA = __shfl_sync(0xffffffffu, PA, srcA);
    int srcB = (lo == 1) ? od : (16 + od);
    float vB = __shfl_sync(0xffffffffu, PB, srcB);
    float vC = __shfl_sync(0xffffffffu, PA, 16 + od);
    float ggv = __shfl_sync(0xffffffffu, gg, od);

    float sumsq;
    if      (lo == 0) sumsq = vA;
    else if (lo == 1) sumsq = vB;
    else if (lo == 2) sumsq = vA + vC;
    else              sumsq = vA + vB;

    out[atom * (NDESC * LMAX) + lane] = 0.5f * (sumsq - ggv);
}

extern "C" void kernel_launch(void* const* d_in, const int* in_sizes, int n_in,
                              void* d_out, int out_size)
{
    const int*   types     = (const int*)d_in[0];
    const float* positions = (const float*)d_in[1];
    const int*   nbrs      = (const int*)d_in[2];
    const float* c_table   = (const float*)d_in[3];
    float*       out       = (float*)d_out;

    const int N = in_sizes[0];
    const int blocks = (N + WPB - 1) / WPB;
    angular_desc_kernel<<<blocks, THREADS>>>(types, positions, nbrs, c_table, out, N);
}